// round 1
// baseline (speedup 1.0000x reference)
#include <cuda_runtime.h>
#include <math.h>

#define D_MODEL 768
#define D_INNER 1536
#define NBATCH 4
#define LSEQ 2048
#define MROWS (NBATCH * LSEQ)      // 8192
#define DT_RANK 48
#define D_STATE 16
#define XDBL_N (DT_RANK + 2 * D_STATE)   // 80

// -------- scratch (device globals; no allocation allowed) --------
__device__ float g_xr[(size_t)MROWS * 2 * D_INNER];   // in_proj output [8192, 3072]
__device__ float g_h[(size_t)MROWS * D_INNER];        // conv+silu output [8192, 1536]
__device__ float g_xdbl[(size_t)MROWS * XDBL_N];      // x_proj output [8192, 80]
__device__ float g_delta[(size_t)MROWS * D_INNER];    // softplus(dt_proj) [8192, 1536]
__device__ float g_y[(size_t)MROWS * D_INNER];        // gated scan output [8192, 1536]

__device__ __forceinline__ float siluf(float v) { return v / (1.f + __expf(-v)); }
__device__ __forceinline__ float softplusf(float v) {
    return v > 20.f ? v : log1pf(__expf(v));
}

// ============================================================================
// Generic NT SGEMM: C[M,N] = A[M,K] * B[N,K]^T  (+bias, +softplus)
// A row-major with leading dim lda, B row-major with leading dim ldb, C ldc=N.
// Requirements: M % 128 == 0, K % 8 == 0, lda/ldb % 4 == 0. N arbitrary (guarded).
// 128x128 tile, BK=8, 256 threads, 8x8 per-thread microtile split as 2x2 of 4x4
// at offsets {0,64} so smem reads are conflict-free float4s.
// ============================================================================
__global__ __launch_bounds__(256, 2) void sgemm_nt(
    int M, int N, int K,
    const float* __restrict__ A, int lda,
    const float* __restrict__ B, int ldb,
    const float* __restrict__ bias,
    float* __restrict__ C, int act)
{
    __shared__ __align__(16) float As[8][132];
    __shared__ __align__(16) float Bs[8][132];

    const int tid = threadIdx.x;
    const int tx = tid & 15;   // 0..15 (col group)
    const int ty = tid >> 4;   // 0..15 (row group)
    const int row0 = blockIdx.y * 128;
    const int col0 = blockIdx.x * 128;

    // load assignments: 128 rows x 8 k per tile, one float4 per thread
    const int lr = tid >> 1;          // 0..127
    const int lc = (tid & 1) * 4;     // 0 or 4

    const float* Ag = A + (size_t)(row0 + lr) * lda + lc;
    const float* Bg = B + (size_t)(col0 + lr) * ldb + lc;
    const bool bval = (col0 + lr) < N;

    float acc[8][8];
#pragma unroll
    for (int i = 0; i < 8; i++)
#pragma unroll
        for (int j = 0; j < 8; j++) acc[i][j] = 0.f;

    for (int k0 = 0; k0 < K; k0 += 8) {
        float4 av = *(const float4*)(Ag + k0);
        float4 bv = make_float4(0.f, 0.f, 0.f, 0.f);
        if (bval) bv = *(const float4*)(Bg + k0);
        As[lc + 0][lr] = av.x; As[lc + 1][lr] = av.y;
        As[lc + 2][lr] = av.z; As[lc + 3][lr] = av.w;
        Bs[lc + 0][lr] = bv.x; Bs[lc + 1][lr] = bv.y;
        Bs[lc + 2][lr] = bv.z; Bs[lc + 3][lr] = bv.w;
        __syncthreads();
#pragma unroll
        for (int kk = 0; kk < 8; kk++) {
            float a[8], b[8];
            *(float4*)(a)     = *(const float4*)&As[kk][ty * 4];
            *(float4*)(a + 4) = *(const float4*)&As[kk][64 + ty * 4];
            *(float4*)(b)     = *(const float4*)&Bs[kk][tx * 4];
            *(float4*)(b + 4) = *(const float4*)&Bs[kk][64 + tx * 4];
#pragma unroll
            for (int i = 0; i < 8; i++)
#pragma unroll
                for (int j = 0; j < 8; j++)
                    acc[i][j] = fmaf(a[i], b[j], acc[i][j]);
        }
        __syncthreads();
    }

#pragma unroll
    for (int i = 0; i < 8; i++) {
        const int r = row0 + ((i < 4) ? (ty * 4 + i) : (64 + ty * 4 + i - 4));
#pragma unroll
        for (int j = 0; j < 8; j++) {
            const int c = col0 + ((j < 4) ? (tx * 4 + j) : (64 + tx * 4 + j - 4));
            if (c < N) {
                float v = acc[i][j];
                if (bias) v += bias[c];
                if (act == 1) v = softplusf(v);
                C[(size_t)r * N + c] = v;
            }
        }
    }
}

// ============================================================================
// Depthwise causal conv1d (d_conv=4) + bias + SiLU.
// Input:  g_xr[:, 0:1536] (row stride 3072). Output: g_h [8192,1536].
// ============================================================================
__global__ __launch_bounds__(256) void conv_silu_kernel(
    const float* __restrict__ cw, const float* __restrict__ cb)
{
    const int idx = blockIdx.x * 256 + threadIdx.x;
    const int d = idx % D_INNER;
    const int m = idx / D_INNER;
    const int l = m & (LSEQ - 1);
    const float* base = g_xr + (size_t)m * (2 * D_INNER) + d;
    float acc = cb[d];
#pragma unroll
    for (int j = 0; j < 4; j++) {
        const int ll = l - 3 + j;
        if (ll >= 0)
            acc = fmaf(cw[d * 4 + j], base[(ptrdiff_t)(j - 3) * (2 * D_INNER)], acc);
    }
    g_h[idx] = siluf(acc);
}

// ============================================================================
// Skinny GEMM: g_xdbl[8192,80] = g_h[8192,1536] @ W_x[80,1536]^T
// Tile: 64 rows x 80 cols per block, 256 threads (64 rows x 4 col-groups of 20).
// ============================================================================
__global__ __launch_bounds__(256) void gemm_xdbl_kernel(const float* __restrict__ Wx)
{
    __shared__ __align__(16) float As[16][68];
    __shared__ __align__(16) float Bs[16][80];

    const int tid = threadIdx.x;
    const int m0 = blockIdx.x * 64;
    const int tm = tid & 63;
    const int tg = tid >> 6;             // 0..3 -> cols tg*20 .. +19
    const int arow = tid >> 2;           // 0..63
    const int acol = (tid & 3) * 4;      // 0,4,8,12

    float acc[20];
#pragma unroll
    for (int j = 0; j < 20; j++) acc[j] = 0.f;

    const float* Ag = g_h + (size_t)(m0 + arow) * D_INNER + acol;

    for (int k0 = 0; k0 < D_INNER; k0 += 16) {
        float4 av = *(const float4*)(Ag + k0);
        As[acol + 0][arow] = av.x; As[acol + 1][arow] = av.y;
        As[acol + 2][arow] = av.z; As[acol + 3][arow] = av.w;
        // load W_x tile: 80 n-rows x 16 k, k-vectorized (320 float4 loads)
#pragma unroll
        for (int s = 0; s < 2; s++) {
            const int i = s * 256 + tid;
            if (i < 320) {
                const int nn = i >> 2;
                const int kq = (i & 3) * 4;
                float4 bv = *(const float4*)(Wx + (size_t)nn * D_INNER + k0 + kq);
                Bs[kq + 0][nn] = bv.x; Bs[kq + 1][nn] = bv.y;
                Bs[kq + 2][nn] = bv.z; Bs[kq + 3][nn] = bv.w;
            }
        }
        __syncthreads();
#pragma unroll
        for (int kk = 0; kk < 16; kk++) {
            const float a = As[kk][tm];
            float bvals[20];
            const float* brow = &Bs[kk][tg * 20];
            *(float4*)(bvals)      = *(const float4*)(brow);
            *(float4*)(bvals + 4)  = *(const float4*)(brow + 4);
            *(float4*)(bvals + 8)  = *(const float4*)(brow + 8);
            *(float4*)(bvals + 12) = *(const float4*)(brow + 12);
            *(float4*)(bvals + 16) = *(const float4*)(brow + 16);
#pragma unroll
            for (int j = 0; j < 20; j++) acc[j] = fmaf(a, bvals[j], acc[j]);
        }
        __syncthreads();
    }

    float* Cp = g_xdbl + (size_t)(m0 + tm) * XDBL_N + tg * 20;
#pragma unroll
    for (int j = 0; j < 20; j++) Cp[j] = acc[j];
}

// ============================================================================
// Selective scan, fused with +u*D residual and *silu(res) gating.
// Thread = (channel d, state n). 16 lanes per channel, 2 channels per warp.
// Block = 256 threads = 16 consecutive d channels; grid (96, 4 batches).
// state_t = exp(delta_t * A[d,n]) * state_{t-1} + delta_t * B_t[n] * u_t
// y_t[d]  = sum_n state_t * C_t[n];  out = (y + u*D[d]) * silu(res)
// ============================================================================
__global__ __launch_bounds__(256) void scan_kernel(
    const float* __restrict__ A_log, const float* __restrict__ Dp)
{
    const int lane = threadIdx.x & 31;
    const int warp = threadIdx.x >> 5;
    const int n = lane & 15;
    const int d = blockIdx.x * 16 + warp * 2 + (lane >> 4);
    const int b = blockIdx.y;

    const float Alg = -__expf(A_log[d * D_STATE + n]) * 1.4426950408889634f;
    const float Dd = Dp[d];
    float state = 0.f;

    const float* dptr = g_delta + (size_t)b * LSEQ * D_INNER + d;
    const float* uptr = g_h + (size_t)b * LSEQ * D_INNER + d;
    const float* rptr = g_xr + (size_t)b * LSEQ * (2 * D_INNER) + D_INNER + d;
    const float* xdp = g_xdbl + (size_t)b * LSEQ * XDBL_N;
    float* yptr = g_y + (size_t)b * LSEQ * D_INNER + d;

#pragma unroll 2
    for (int t = 0; t < LSEQ; t++) {
        const float dt = __ldg(dptr);
        const float ut = __ldg(uptr);
        const float Bn = __ldg(xdp + DT_RANK + n);
        const float Cn = __ldg(xdp + DT_RANK + D_STATE + n);

        const float dA = exp2f(dt * Alg);
        state = fmaf(dA, state, dt * Bn * ut);

        float p = state * Cn;
        p += __shfl_xor_sync(0xffffffffu, p, 1);
        p += __shfl_xor_sync(0xffffffffu, p, 2);
        p += __shfl_xor_sync(0xffffffffu, p, 4);
        p += __shfl_xor_sync(0xffffffffu, p, 8);

        if (n == 0) {
            const float rv = __ldg(rptr);
            *yptr = (p + ut * Dd) * siluf(rv);
        }
        dptr += D_INNER;
        uptr += D_INNER;
        rptr += 2 * D_INNER;
        xdp += XDBL_N;
        yptr += D_INNER;
    }
}

// ============================================================================
// kernel_launch
// Inputs (metadata order): x, W_in, conv_w, conv_b, W_x, W_dt, b_dt, A_log, D, W_out
// ============================================================================
extern "C" void kernel_launch(void* const* d_in, const int* in_sizes, int n_in,
                              void* d_out, int out_size)
{
    const float* x      = (const float*)d_in[0];
    const float* W_in   = (const float*)d_in[1];
    const float* conv_w = (const float*)d_in[2];
    const float* conv_b = (const float*)d_in[3];
    const float* W_x    = (const float*)d_in[4];
    const float* W_dt   = (const float*)d_in[5];
    const float* b_dt   = (const float*)d_in[6];
    const float* A_log  = (const float*)d_in[7];
    const float* Dp     = (const float*)d_in[8];
    const float* W_out  = (const float*)d_in[9];
    float* out = (float*)d_out;

    float *xr, *xdbl, *delta, *y;
    cudaGetSymbolAddress((void**)&xr, g_xr);
    cudaGetSymbolAddress((void**)&xdbl, g_xdbl);
    cudaGetSymbolAddress((void**)&delta, g_delta);
    cudaGetSymbolAddress((void**)&y, g_y);

    // 1) in_proj: xr[8192,3072] = x[8192,768] @ W_in[3072,768]^T
    sgemm_nt<<<dim3(2 * D_INNER / 128, MROWS / 128), 256>>>(
        MROWS, 2 * D_INNER, D_MODEL, x, D_MODEL, W_in, D_MODEL, nullptr, xr, 0);

    // 2) depthwise causal conv + silu -> g_h
    conv_silu_kernel<<<(MROWS * D_INNER) / 256, 256>>>(conv_w, conv_b);

    // 3) x_proj: g_xdbl[8192,80] = g_h @ W_x^T
    gemm_xdbl_kernel<<<MROWS / 64, 256>>>(W_x);

    // 4) dt_proj + softplus: delta[8192,1536] = softplus(xdbl[:, :48] @ W_dt^T + b_dt)
    sgemm_nt<<<dim3(D_INNER / 128, MROWS / 128), 256>>>(
        MROWS, D_INNER, DT_RANK, xdbl, XDBL_N, W_dt, DT_RANK, b_dt, delta, 1);

    // 5) selective scan + D-residual + gating -> g_y
    scan_kernel<<<dim3(D_INNER / 16, NBATCH), 256>>>(A_log, Dp);

    // 6) out_proj: out[8192,768] = g_y @ W_out[768,1536]^T
    sgemm_nt<<<dim3(D_MODEL / 128, MROWS / 128), 256>>>(
        MROWS, D_MODEL, D_INNER, y, D_INNER, W_out, D_INNER, nullptr, out, 0);
}

// round 2
// speedup vs baseline: 1.3189x; 1.3189x over previous
#include <cuda_runtime.h>
#include <math.h>

#define D_MODEL 768
#define D_INNER 1536
#define NBATCH 4
#define LSEQ 2048
#define MROWS (NBATCH * LSEQ)      // 8192
#define DT_RANK 48
#define D_STATE 16
#define XDBL_N (DT_RANK + 2 * D_STATE)   // 80

// -------- scratch (device globals; no allocation allowed) --------
__device__ float g_xr[(size_t)MROWS * 2 * D_INNER];   // in_proj output [8192, 3072]
__device__ float g_h[(size_t)MROWS * D_INNER];        // conv+silu output [8192, 1536]
__device__ float g_xdbl[(size_t)MROWS * XDBL_N];      // x_proj output [8192, 80]
__device__ float g_delta[(size_t)MROWS * D_INNER];    // softplus(dt_proj) [8192, 1536]
__device__ float g_y[(size_t)MROWS * D_INNER];        // gated scan output [8192, 1536]

__device__ __forceinline__ float siluf(float v) { return v / (1.f + __expf(-v)); }
__device__ __forceinline__ float softplusf(float v) {
    return v > 20.f ? v : log1pf(__expf(v));
}
__device__ __forceinline__ unsigned f2tf32(float f) {
    unsigned u;
    asm("cvt.rna.tf32.f32 %0, %1;" : "=r"(u) : "f"(f));
    return u;
}

// ============================================================================
// TF32 tensor-core NT GEMM: C[M,N] = A[M,K] * B[N,K]^T  (+bias, +softplus)
// Requirements: M%128==0, N%128==0, K%16==0, lda/ldb%4==0.
// Block 128x128, BK=16, 256 threads, 8 warps as 2(M)x4(N), warp tile 64x32.
// mma.sync.m16n8k8.tf32 with fragments via ldmatrix.m8n8.x4.b16 on XOR-swizzled
// k-contiguous smem (rows of 16 floats; c4 ^= (row>>1)&3).
// ============================================================================
__global__ __launch_bounds__(256) void tf32_gemm_nt(
    int M, int N, int K,
    const float* __restrict__ A, int lda,
    const float* __restrict__ B, int ldb,
    const float* __restrict__ bias,
    float* __restrict__ C, int act)
{
    // A buffers: [0,2048),[2048,4096) ; B buffers: [4096,6144),[6144,8192) (words)
    __shared__ __align__(16) unsigned sm[8192];

    const int tid = threadIdx.x;
    const int lane = tid & 31;
    const int warp = tid >> 5;
    const int wm = (warp & 1) * 64;
    const int wn = (warp >> 1) * 32;
    const int row0 = blockIdx.y * 128;
    const int col0 = blockIdx.x * 128;

    // ---- global load assignment: thread -> (row lr_, float4-col lc_), 2 rows (r, r+64)
    const int lr_ = tid >> 2;
    const int lc_ = tid & 3;
    const float* pa = A + (size_t)(row0 + lr_) * lda + lc_ * 4;
    const float* pb = B + (size_t)(col0 + lr_) * ldb + lc_ * 4;
    const unsigned soff = lr_ * 16 + ((lc_ ^ ((lr_ >> 1) & 3)) << 2);  // words

    // ---- ldmatrix per-lane byte offsets (buffer 0); add 8192*buf at use
    const int g = lane >> 3;        // tile index within x4
    const int lrow = lane & 7;
    unsigned aOff[2][4], bOff[2][2];
#pragma unroll
    for (int s = 0; s < 2; s++) {
#pragma unroll
        for (int mi = 0; mi < 4; mi++) {
            int row = wm + mi * 16 + (g & 1) * 8 + lrow;
            int c16 = s * 2 + (g >> 1);
            aOff[s][mi] = (unsigned)((row * 16 + ((c16 ^ ((row >> 1) & 3)) << 2)) * 4);
        }
#pragma unroll
        for (int p = 0; p < 2; p++) {
            int row = wn + p * 16 + (g & 1) * 8 + lrow;
            int c16 = s * 2 + (g >> 1);
            bOff[s][p] = (unsigned)((row * 16 + ((c16 ^ ((row >> 1) & 3)) << 2)) * 4);
        }
    }
    const unsigned smA = (unsigned)__cvta_generic_to_shared(sm);
    const unsigned smB = smA + 16384;

    float acc[4][4][4];
#pragma unroll
    for (int mi = 0; mi < 4; mi++)
#pragma unroll
        for (int ni = 0; ni < 4; ni++)
#pragma unroll
            for (int q = 0; q < 4; q++) acc[mi][ni][q] = 0.f;

    float4 fa0, fa1, fb0, fb1;

#define LDG_STAGE(k0) do {                                        \
        fa0 = *(const float4*)(pa + (k0));                         \
        fa1 = *(const float4*)(pa + (k0) + (size_t)64 * lda);      \
        fb0 = *(const float4*)(pb + (k0));                         \
        fb1 = *(const float4*)(pb + (k0) + (size_t)64 * ldb);      \
    } while (0)

#define STS_STAGE(buf) do {                                                        \
        unsigned* dA = sm + (buf) * 2048 + soff;                                    \
        unsigned* dB = sm + 4096 + (buf) * 2048 + soff;                             \
        uint4 q;                                                                    \
        q.x = f2tf32(fa0.x); q.y = f2tf32(fa0.y); q.z = f2tf32(fa0.z); q.w = f2tf32(fa0.w); \
        *(uint4*)dA = q;                                                            \
        q.x = f2tf32(fa1.x); q.y = f2tf32(fa1.y); q.z = f2tf32(fa1.z); q.w = f2tf32(fa1.w); \
        *(uint4*)(dA + 1024) = q;                                                   \
        q.x = f2tf32(fb0.x); q.y = f2tf32(fb0.y); q.z = f2tf32(fb0.z); q.w = f2tf32(fb0.w); \
        *(uint4*)dB = q;                                                            \
        q.x = f2tf32(fb1.x); q.y = f2tf32(fb1.y); q.z = f2tf32(fb1.z); q.w = f2tf32(fb1.w); \
        *(uint4*)(dB + 1024) = q;                                                   \
    } while (0)

    const int nIter = K / 16;

    LDG_STAGE(0);
    STS_STAGE(0);
    __syncthreads();
    if (nIter > 1) LDG_STAGE(16);

    for (int it = 0; it < nIter; it++) {
        const unsigned bufA = smA + (it & 1) * 8192;
        const unsigned bufB = smB + (it & 1) * 8192;
#pragma unroll
        for (int s = 0; s < 2; s++) {
            unsigned a[4][4], b[2][4];
#pragma unroll
            for (int mi = 0; mi < 4; mi++) {
                unsigned addr = bufA + aOff[s][mi];
                asm volatile("ldmatrix.sync.aligned.m8n8.x4.shared.b16 {%0,%1,%2,%3}, [%4];"
                             : "=r"(a[mi][0]), "=r"(a[mi][1]), "=r"(a[mi][2]), "=r"(a[mi][3])
                             : "r"(addr));
            }
#pragma unroll
            for (int p = 0; p < 2; p++) {
                unsigned addr = bufB + bOff[s][p];
                asm volatile("ldmatrix.sync.aligned.m8n8.x4.shared.b16 {%0,%1,%2,%3}, [%4];"
                             : "=r"(b[p][0]), "=r"(b[p][1]), "=r"(b[p][2]), "=r"(b[p][3])
                             : "r"(addr));
            }
            // b[p] = { b0(n8#0), b0(n8#1), b1(n8#0), b1(n8#1) } within the n16 pair
#pragma unroll
            for (int mi = 0; mi < 4; mi++)
#pragma unroll
                for (int ni = 0; ni < 4; ni++) {
                    unsigned bb0 = b[ni >> 1][(ni & 1)];
                    unsigned bb1 = b[ni >> 1][(ni & 1) + 2];
                    asm volatile(
                        "mma.sync.aligned.m16n8k8.row.col.f32.tf32.tf32.f32 "
                        "{%0,%1,%2,%3}, {%4,%5,%6,%7}, {%8,%9}, {%0,%1,%2,%3};"
                        : "+f"(acc[mi][ni][0]), "+f"(acc[mi][ni][1]),
                          "+f"(acc[mi][ni][2]), "+f"(acc[mi][ni][3])
                        : "r"(a[mi][0]), "r"(a[mi][1]), "r"(a[mi][2]), "r"(a[mi][3]),
                          "r"(bb0), "r"(bb1));
                }
        }
        if (it + 1 < nIter) STS_STAGE((it + 1) & 1);
        __syncthreads();
        if (it + 2 < nIter) LDG_STAGE(16 * (it + 2));
    }

    // ---- epilogue
#pragma unroll
    for (int mi = 0; mi < 4; mi++) {
        const int r = row0 + wm + mi * 16 + (lane >> 2);
#pragma unroll
        for (int ni = 0; ni < 4; ni++) {
            const int c = col0 + wn + ni * 8 + (lane & 3) * 2;
            float2 v0 = make_float2(acc[mi][ni][0], acc[mi][ni][1]);
            float2 v1 = make_float2(acc[mi][ni][2], acc[mi][ni][3]);
            if (bias) {
                float b0 = bias[c], b1 = bias[c + 1];
                v0.x += b0; v0.y += b1; v1.x += b0; v1.y += b1;
            }
            if (act == 1) {
                v0.x = softplusf(v0.x); v0.y = softplusf(v0.y);
                v1.x = softplusf(v1.x); v1.y = softplusf(v1.y);
            }
            *(float2*)&C[(size_t)r * N + c] = v0;
            *(float2*)&C[(size_t)(r + 8) * N + c] = v1;
        }
    }
#undef LDG_STAGE
#undef STS_STAGE
}

// ============================================================================
// Depthwise causal conv1d (d_conv=4) + bias + SiLU.
// Input:  g_xr[:, 0:1536] (row stride 3072). Output: g_h [8192,1536].
// ============================================================================
__global__ __launch_bounds__(256) void conv_silu_kernel(
    const float* __restrict__ cw, const float* __restrict__ cb)
{
    const int idx = blockIdx.x * 256 + threadIdx.x;
    const int d = idx % D_INNER;
    const int m = idx / D_INNER;
    const int l = m & (LSEQ - 1);
    const float* base = g_xr + (size_t)m * (2 * D_INNER) + d;
    float acc = cb[d];
#pragma unroll
    for (int j = 0; j < 4; j++) {
        const int ll = l - 3 + j;
        if (ll >= 0)
            acc = fmaf(cw[d * 4 + j], base[(ptrdiff_t)(j - 3) * (2 * D_INNER)], acc);
    }
    g_h[idx] = siluf(acc);
}

// ============================================================================
// Skinny GEMM: g_xdbl[8192,80] = g_h[8192,1536] @ W_x[80,1536]^T   (fp32)
// ============================================================================
__global__ __launch_bounds__(256) void gemm_xdbl_kernel(const float* __restrict__ Wx)
{
    __shared__ __align__(16) float As[16][68];
    __shared__ __align__(16) float Bs[16][80];

    const int tid = threadIdx.x;
    const int m0 = blockIdx.x * 64;
    const int tm = tid & 63;
    const int tg = tid >> 6;             // 0..3 -> cols tg*20 .. +19
    const int arow = tid >> 2;           // 0..63
    const int acol = (tid & 3) * 4;      // 0,4,8,12

    float acc[20];
#pragma unroll
    for (int j = 0; j < 20; j++) acc[j] = 0.f;

    const float* Ag = g_h + (size_t)(m0 + arow) * D_INNER + acol;

    for (int k0 = 0; k0 < D_INNER; k0 += 16) {
        float4 av = *(const float4*)(Ag + k0);
        As[acol + 0][arow] = av.x; As[acol + 1][arow] = av.y;
        As[acol + 2][arow] = av.z; As[acol + 3][arow] = av.w;
#pragma unroll
        for (int s = 0; s < 2; s++) {
            const int i = s * 256 + tid;
            if (i < 320) {
                const int nn = i >> 2;
                const int kq = (i & 3) * 4;
                float4 bv = *(const float4*)(Wx + (size_t)nn * D_INNER + k0 + kq);
                Bs[kq + 0][nn] = bv.x; Bs[kq + 1][nn] = bv.y;
                Bs[kq + 2][nn] = bv.z; Bs[kq + 3][nn] = bv.w;
            }
        }
        __syncthreads();
#pragma unroll
        for (int kk = 0; kk < 16; kk++) {
            const float a = As[kk][tm];
            float bvals[20];
            const float* brow = &Bs[kk][tg * 20];
            *(float4*)(bvals)      = *(const float4*)(brow);
            *(float4*)(bvals + 4)  = *(const float4*)(brow + 4);
            *(float4*)(bvals + 8)  = *(const float4*)(brow + 8);
            *(float4*)(bvals + 12) = *(const float4*)(brow + 12);
            *(float4*)(bvals + 16) = *(const float4*)(brow + 16);
#pragma unroll
            for (int j = 0; j < 20; j++) acc[j] = fmaf(a, bvals[j], acc[j]);
        }
        __syncthreads();
    }

    float* Cp = g_xdbl + (size_t)(m0 + tm) * XDBL_N + tg * 20;
#pragma unroll
    for (int j = 0; j < 20; j++) Cp[j] = acc[j];
}

// ============================================================================
// Selective scan, fused with +u*D residual and *silu(res) gating.
// Thread = (channel d, state n). 16 lanes per channel, 2 channels per warp.
// ============================================================================
__global__ __launch_bounds__(256) void scan_kernel(
    const float* __restrict__ A_log, const float* __restrict__ Dp)
{
    const int lane = threadIdx.x & 31;
    const int warp = threadIdx.x >> 5;
    const int n = lane & 15;
    const int d = blockIdx.x * 16 + warp * 2 + (lane >> 4);
    const int b = blockIdx.y;

    const float Alg = -__expf(A_log[d * D_STATE + n]) * 1.4426950408889634f;
    const float Dd = Dp[d];
    float state = 0.f;

    const float* dptr = g_delta + (size_t)b * LSEQ * D_INNER + d;
    const float* uptr = g_h + (size_t)b * LSEQ * D_INNER + d;
    const float* rptr = g_xr + (size_t)b * LSEQ * (2 * D_INNER) + D_INNER + d;
    const float* xdp = g_xdbl + (size_t)b * LSEQ * XDBL_N;
    float* yptr = g_y + (size_t)b * LSEQ * D_INNER + d;

#pragma unroll 2
    for (int t = 0; t < LSEQ; t++) {
        const float dt = __ldg(dptr);
        const float ut = __ldg(uptr);
        const float Bn = __ldg(xdp + DT_RANK + n);
        const float Cn = __ldg(xdp + DT_RANK + D_STATE + n);

        const float dA = exp2f(dt * Alg);
        state = fmaf(dA, state, dt * Bn * ut);

        float p = state * Cn;
        p += __shfl_xor_sync(0xffffffffu, p, 1);
        p += __shfl_xor_sync(0xffffffffu, p, 2);
        p += __shfl_xor_sync(0xffffffffu, p, 4);
        p += __shfl_xor_sync(0xffffffffu, p, 8);

        if (n == 0) {
            const float rv = __ldg(rptr);
            *yptr = (p + ut * Dd) * siluf(rv);
        }
        dptr += D_INNER;
        uptr += D_INNER;
        rptr += 2 * D_INNER;
        xdp += XDBL_N;
        yptr += D_INNER;
    }
}

// ============================================================================
// kernel_launch
// Inputs: x, W_in, conv_w, conv_b, W_x, W_dt, b_dt, A_log, D, W_out
// ============================================================================
extern "C" void kernel_launch(void* const* d_in, const int* in_sizes, int n_in,
                              void* d_out, int out_size)
{
    const float* x      = (const float*)d_in[0];
    const float* W_in   = (const float*)d_in[1];
    const float* conv_w = (const float*)d_in[2];
    const float* conv_b = (const float*)d_in[3];
    const float* W_x    = (const float*)d_in[4];
    const float* W_dt   = (const float*)d_in[5];
    const float* b_dt   = (const float*)d_in[6];
    const float* A_log  = (const float*)d_in[7];
    const float* Dp     = (const float*)d_in[8];
    const float* W_out  = (const float*)d_in[9];
    float* out = (float*)d_out;

    float *xr, *xdbl, *delta, *y;
    cudaGetSymbolAddress((void**)&xr, g_xr);
    cudaGetSymbolAddress((void**)&xdbl, g_xdbl);
    cudaGetSymbolAddress((void**)&delta, g_delta);
    cudaGetSymbolAddress((void**)&y, g_y);

    // 1) in_proj: xr[8192,3072] = x[8192,768] @ W_in[3072,768]^T   (tf32 TC)
    tf32_gemm_nt<<<dim3(2 * D_INNER / 128, MROWS / 128), 256>>>(
        MROWS, 2 * D_INNER, D_MODEL, x, D_MODEL, W_in, D_MODEL, nullptr, xr, 0);

    // 2) depthwise causal conv + silu -> g_h
    conv_silu_kernel<<<(MROWS * D_INNER) / 256, 256>>>(conv_w, conv_b);

    // 3) x_proj: g_xdbl[8192,80] = g_h @ W_x^T  (fp32, keeps B/C/dt inputs exact)
    gemm_xdbl_kernel<<<MROWS / 64, 256>>>(W_x);

    // 4) dt_proj + softplus (tf32 TC): delta = softplus(xdbl[:, :48] @ W_dt^T + b_dt)
    tf32_gemm_nt<<<dim3(D_INNER / 128, MROWS / 128), 256>>>(
        MROWS, D_INNER, DT_RANK, xdbl, XDBL_N, W_dt, DT_RANK, b_dt, delta, 1);

    // 5) selective scan + D-residual + gating -> g_y
    scan_kernel<<<dim3(D_INNER / 16, NBATCH), 256>>>(A_log, Dp);

    // 6) out_proj (tf32 TC): out[8192,768] = g_y @ W_out[768,1536]^T
    tf32_gemm_nt<<<dim3(D_MODEL / 128, MROWS / 128), 256>>>(
        MROWS, D_MODEL, D_INNER, y, D_INNER, W_out, D_INNER, nullptr, out, 0);
}